// round 2
// baseline (speedup 1.0000x reference)
#include <cuda_runtime.h>
#include <math.h>

#define BB 64
#define SS 512
#define II 1024
#define HH 1024
#define NCTA_SCAN 144          // 48 tiles x 3 K-splits; < 148 SMs => co-resident
#define NTHR_SCAN 256
#define SCAN_THREADS (NCTA_SCAN * NTHR_SCAN)

// Scratch (device globals — no allocation allowed anywhere).
__device__ float g_xg[3][SS][BB][HH];          // input-side pre-activations (f,o,c)
__device__ float g_h[BB * HH];
__device__ float g_c[BB * HH];
__device__ float g_part[3][3][BB][HH];         // [ksplit][gate][b][h]

// software grid barrier state
__device__ unsigned g_bar_count = 0;
__device__ unsigned g_bar_gen   = 0;

__device__ __forceinline__ void grid_sync() {
    __threadfence();
    __syncthreads();
    if (threadIdx.x == 0) {
        unsigned my = *(volatile unsigned*)&g_bar_gen;
        if (atomicAdd(&g_bar_count, 1) == NCTA_SCAN - 1) {
            g_bar_count = 0;
            __threadfence();
            atomicExch(&g_bar_gen, my + 1);
        } else {
            while (*(volatile unsigned*)&g_bar_gen == my) { }
        }
    }
    __syncthreads();
    __threadfence();
}

// ---------------------------------------------------------------------------
// K1: input-side GEMM. M = B*S = 32768, N = 3x1024, K = 1024.
// 128x128x8 tiles, 256 threads, 8x8/thread, LDS.128 fragment loads.
// Epilogue adds bias, scatters into g_xg time-major.
// ---------------------------------------------------------------------------
__global__ __launch_bounds__(256) void k_ingemm(
    const float* __restrict__ X,
    const float* __restrict__ Wf, const float* __restrict__ Wo, const float* __restrict__ Wc,
    const float* __restrict__ bf, const float* __restrict__ bo, const float* __restrict__ bc)
{
    __shared__ float As[8][128];
    __shared__ float Bs[8][128];

    const int bm = blockIdx.x;           // 0..255
    const int bn = blockIdx.y;           // 0..23
    const int g  = bn >> 3;
    const int col0 = (bn & 7) << 7;

    const float* Wg = (g == 0) ? Wf : (g == 1) ? Wo : Wc;
    const float* bg = (g == 0) ? bf : (g == 1) ? bo : bc;

    const int tid  = threadIdx.x;
    const int tx   = tid & 15;
    const int ty   = tid >> 4;
    const int lrow = tid >> 1;           // 0..127
    const int lk   = (tid & 1) << 2;     // 0 or 4

    const float* Ap = X  + (size_t)(bm * 128 + lrow) * II + lk;
    const float* Bp = Wg + (size_t)(col0 + lrow) * II + lk;

    float acc[8][8] = {};

    for (int k0 = 0; k0 < II; k0 += 8) {
        float4 a = *(const float4*)(Ap + k0);
        float4 b = *(const float4*)(Bp + k0);
        __syncthreads();
        As[lk + 0][lrow] = a.x; As[lk + 1][lrow] = a.y;
        As[lk + 2][lrow] = a.z; As[lk + 3][lrow] = a.w;
        Bs[lk + 0][lrow] = b.x; Bs[lk + 1][lrow] = b.y;
        Bs[lk + 2][lrow] = b.z; Bs[lk + 3][lrow] = b.w;
        __syncthreads();
        #pragma unroll
        for (int k = 0; k < 8; k++) {
            float4 a0 = *(const float4*)&As[k][ty * 8];
            float4 a1 = *(const float4*)&As[k][ty * 8 + 4];
            float4 b0 = *(const float4*)&Bs[k][tx * 8];
            float4 b1 = *(const float4*)&Bs[k][tx * 8 + 4];
            float ar[8] = {a0.x, a0.y, a0.z, a0.w, a1.x, a1.y, a1.z, a1.w};
            float br[8] = {b0.x, b0.y, b0.z, b0.w, b1.x, b1.y, b1.z, b1.w};
            #pragma unroll
            for (int i = 0; i < 8; i++)
                #pragma unroll
                for (int j = 0; j < 8; j++)
                    acc[i][j] = fmaf(ar[i], br[j], acc[i][j]);
        }
    }

    #pragma unroll
    for (int i = 0; i < 8; i++) {
        int m  = bm * 128 + ty * 8 + i;
        int b_ = m >> 9;
        int s_ = m & 511;
        float* dst = &g_xg[g][s_][b_][col0 + tx * 8];
        #pragma unroll
        for (int j = 0; j < 8; j++)
            dst[j] = acc[i][j] + bg[col0 + tx * 8 + j];
    }
}

// ---------------------------------------------------------------------------
// K2: persistent scan. 144 CTAs x 256 threads, all co-resident.
// Per step: phase A = recurrent GEMM partials (each CTA one (gate,ntile,ksplit)
// 64x64 tile over a 344/344/336 K-chunk), barrier, phase B = reduce + gates +
// state update + output write, barrier. Start: zero h/c. End: tail h,c.
// ---------------------------------------------------------------------------
__global__ __launch_bounds__(NTHR_SCAN) void k_scan(
    const float* __restrict__ Uf, const float* __restrict__ Uo, const float* __restrict__ Uc,
    float* __restrict__ out)
{
    __shared__ float As[8][64];
    __shared__ float Bs[8][64];

    const int cta  = blockIdx.x;         // 0..143
    const int tile = cta % 48;
    const int ks   = cta / 48;           // 0..2
    const int gate = tile >> 4;
    const int col0 = (tile & 15) << 6;
    const int kbeg = ks * 344;           // 0, 344, 688
    const int klen = (ks < 2) ? 344 : 336;

    const float* Ug = (gate == 0) ? Uf : (gate == 1) ? Uo : Uc;

    const int tid  = threadIdx.x;
    const int tx   = tid & 15;
    const int ty   = tid >> 4;
    const int lrow = tid >> 2;           // 0..63
    const int lk   = (tid & 3) << 1;     // 0,2,4,6

    const int gtid = cta * NTHR_SCAN + tid;

    // zero recurrent state (graph replays must not inherit prior state)
    for (int i = gtid; i < BB * HH; i += SCAN_THREADS) {
        g_h[i] = 0.0f;
        g_c[i] = 0.0f;
    }
    grid_sync();

    const float* Bp = Ug + (size_t)(col0 + lrow) * HH + kbeg + lk;
    const float* Ap_base = g_h + (size_t)lrow * HH + kbeg + lk;

    for (int t = 0; t < SS; t++) {
        // ---- phase A: partial GEMM: g_part[ks][gate] += h @ Ug^T (K-chunk)
        float acc[4][4] = {};
        for (int k0 = 0; k0 < klen; k0 += 8) {
            float2 a = *(const float2*)(Ap_base + k0);
            float2 b = *(const float2*)(Bp + k0);
            __syncthreads();
            As[lk][lrow] = a.x; As[lk + 1][lrow] = a.y;
            Bs[lk][lrow] = b.x; Bs[lk + 1][lrow] = b.y;
            __syncthreads();
            #pragma unroll
            for (int k = 0; k < 8; k++) {
                float4 av = *(const float4*)&As[k][ty * 4];
                float4 bv = *(const float4*)&Bs[k][tx * 4];
                float ar[4] = {av.x, av.y, av.z, av.w};
                float br[4] = {bv.x, bv.y, bv.z, bv.w};
                #pragma unroll
                for (int i = 0; i < 4; i++)
                    #pragma unroll
                    for (int j = 0; j < 4; j++)
                        acc[i][j] = fmaf(ar[i], br[j], acc[i][j]);
            }
        }
        #pragma unroll
        for (int i = 0; i < 4; i++) {
            float* dst = &g_part[ks][gate][ty * 4 + i][col0 + tx * 4];
            #pragma unroll
            for (int j = 0; j < 4; j++) dst[j] = acc[i][j];
        }

        grid_sync();

        // ---- phase B: reduce partials, activations, state update, output
        for (int idx = gtid; idx < BB * HH; idx += SCAN_THREADS) {
            int b_  = idx >> 10;
            int col = idx & 1023;
            float pf = g_xg[0][t][b_][col] + g_part[0][0][b_][col]
                     + g_part[1][0][b_][col] + g_part[2][0][b_][col];
            float po = g_xg[1][t][b_][col] + g_part[0][1][b_][col]
                     + g_part[1][1][b_][col] + g_part[2][1][b_][col];
            float pc = g_xg[2][t][b_][col] + g_part[0][2][b_][col]
                     + g_part[1][2][b_][col] + g_part[2][2][b_][col];
            float f = 1.0f / (1.0f + __expf(-pf));
            float o = 1.0f / (1.0f + __expf(-po));
            float c = f * g_c[idx] + tanhf(pc);
            float h = o * c;
            g_c[idx] = c;
            g_h[idx] = h;
            out[((size_t)b_ * SS + t) * HH + col] = h;
        }

        grid_sync();
    }

    // ---- tail: output tuple is (output[B,S,H], h[1,B,H], c[1,B,H])
    for (int i = gtid; i < BB * HH; i += SCAN_THREADS) {
        out[(size_t)BB * SS * HH + i]           = g_h[i];
        out[(size_t)BB * SS * HH + BB * HH + i] = g_c[i];
    }
}

extern "C" void kernel_launch(void* const* d_in, const int* in_sizes, int n_in,
                              void* d_out, int out_size) {
    const float* X  = (const float*)d_in[0];
    const float* Wf = (const float*)d_in[1];
    const float* Uf = (const float*)d_in[2];
    const float* bf = (const float*)d_in[3];
    // d_in[4..6] = W_i, U_i, b_i — gate i is computed-but-unused in the
    // reference, so we skip it entirely.
    const float* Wo = (const float*)d_in[7];
    const float* Uo = (const float*)d_in[8];
    const float* bo = (const float*)d_in[9];
    const float* Wc = (const float*)d_in[10];
    const float* Uc = (const float*)d_in[11];
    const float* bc = (const float*)d_in[12];
    float* out = (float*)d_out;

    k_ingemm<<<dim3(256, 24), 256>>>(X, Wf, Wo, Wc, bf, bo, bc);
    k_scan<<<NCTA_SCAN, NTHR_SCAN>>>(Uf, Uo, Uc, out);
}

// round 4
// speedup vs baseline: 2.4567x; 2.4567x over previous
#include <cuda_runtime.h>
#include <cuda_bf16.h>
#include <math.h>
#include <stdint.h>

#define BB 64
#define SS 512
#define II 1024
#define HH 1024

#define KSPLIT 8                 // scan K-splits (chunk = 128)
#define KCHUNK 128
#define NCTA_SCAN 96             // 3 gates x 4 coltiles x 8 ksplits
#define NTHR_SCAN 256
#define SCAN_THREADS (NCTA_SCAN * NTHR_SCAN)

// ---------------------------------------------------------------------------
// Device globals (no allocation allowed anywhere)
// ---------------------------------------------------------------------------
__device__ float g_xg[3][SS][BB][HH];           // input-side pre-activations
__device__ float g_h[BB * HH];
__device__ float g_c[BB * HH];
__device__ float g_part[KSPLIT][3][BB][HH];     // recurrent GEMM partials (6MB)
__device__ __nv_bfloat16 g_hb_hi[BB * HH];      // h split into bf16 hi/lo
__device__ __nv_bfloat16 g_hb_lo[BB * HH];

__device__ unsigned g_bar_count = 0;
__device__ unsigned g_bar_gen   = 0;

__device__ __forceinline__ void grid_sync() {
    __threadfence();
    __syncthreads();
    if (threadIdx.x == 0) {
        unsigned my = *(volatile unsigned*)&g_bar_gen;
        if (atomicAdd(&g_bar_count, 1) == NCTA_SCAN - 1) {
            g_bar_count = 0;
            __threadfence();
            atomicExch(&g_bar_gen, my + 1);
        } else {
            while (*(volatile unsigned*)&g_bar_gen == my) { }
        }
    }
    __syncthreads();
    __threadfence();
}

// ---------------------------------------------------------------------------
// HMMA helper: mma.sync m16n8k16 bf16 -> f32 (sm_80+, no arch-a suffix needed)
// ---------------------------------------------------------------------------
#define MMA(d, a0, a1, a2, a3, b0, b1)                                        \
    asm volatile("mma.sync.aligned.m16n8k16.row.col.f32.bf16.bf16.f32 "       \
        "{%0,%1,%2,%3}, {%4,%5,%6,%7}, {%8,%9}, {%0,%1,%2,%3};"               \
        : "+f"((d)[0]), "+f"((d)[1]), "+f"((d)[2]), "+f"((d)[3])              \
        : "r"(a0), "r"(a1), "r"(a2), "r"(a3), "r"(b0), "r"(b1))

// Split two fp32 into packed bf16 hi and lo words
__device__ __forceinline__ void split2(float x0, float x1, uint32_t& hi, uint32_t& lo) {
    __nv_bfloat16 h0 = __float2bfloat16_rn(x0);
    __nv_bfloat16 h1 = __float2bfloat16_rn(x1);
    __nv_bfloat16 l0 = __float2bfloat16_rn(x0 - __bfloat162float(h0));
    __nv_bfloat16 l1 = __float2bfloat16_rn(x1 - __bfloat162float(h1));
    hi = ((uint32_t)__bfloat16_as_ushort(h1) << 16) | (uint32_t)__bfloat16_as_ushort(h0);
    lo = ((uint32_t)__bfloat16_as_ushort(l1) << 16) | (uint32_t)__bfloat16_as_ushort(l0);
}

// ---------------------------------------------------------------------------
// K1: input-side GEMM via HMMA bf16 3-term split.
// M = B*S = 32768, N = 3x1024, K = 1024. CTA tile 128x128, k-step 32.
// 8 warps = 2(m) x 4(n): warp tile 64x32. SMEM pitch 40 bf16 (bank-clean).
// ---------------------------------------------------------------------------
#define IPITCH 40
__global__ __launch_bounds__(256) void k_ingemm(
    const float* __restrict__ X,
    const float* __restrict__ Wf, const float* __restrict__ Wo, const float* __restrict__ Wc,
    const float* __restrict__ bf, const float* __restrict__ bo, const float* __restrict__ bc)
{
    __shared__ __align__(16) uint16_t Ahi[128 * IPITCH], Alo[128 * IPITCH];
    __shared__ __align__(16) uint16_t Bhi[128 * IPITCH], Blo[128 * IPITCH];

    const int bm = blockIdx.x;            // 0..255
    const int bn = blockIdx.y;            // 0..23
    const int g  = bn >> 3;
    const int col0 = (bn & 7) << 7;

    const float* Wg = (g == 0) ? Wf : (g == 1) ? Wo : Wc;
    const float* bg = (g == 0) ? bf : (g == 1) ? bo : bc;

    const int tid  = threadIdx.x;
    const int wid  = tid >> 5;
    const int lane = tid & 31;
    const int gq   = lane >> 2;           // 0..7
    const int tg   = lane & 3;            // 0..3
    const int wm   = wid >> 2;            // 0..1
    const int wn   = wid & 3;             // 0..3

    const int lr = tid >> 1;              // 0..127 (loader row)
    const int lc = (tid & 1) << 4;        // 0 or 16 (loader col base)

    const float* Ap = X  + (size_t)(bm * 128 + lr) * II + lc;
    const float* Bp = Wg + (size_t)(col0 + lr) * II + lc;

    float acc[4][4][4] = {};

    for (int k0 = 0; k0 < II; k0 += 32) {
        __syncthreads();                  // protect prior-iter reads
        #pragma unroll
        for (int v = 0; v < 4; v++) {
            float4 a = *(const float4*)(Ap + k0 + v * 4);
            float4 b = *(const float4*)(Bp + k0 + v * 4);
            uint32_t h, l;
            split2(a.x, a.y, h, l);
            *(uint32_t*)&Ahi[lr * IPITCH + lc + v * 4]     = h;
            *(uint32_t*)&Alo[lr * IPITCH + lc + v * 4]     = l;
            split2(a.z, a.w, h, l);
            *(uint32_t*)&Ahi[lr * IPITCH + lc + v * 4 + 2] = h;
            *(uint32_t*)&Alo[lr * IPITCH + lc + v * 4 + 2] = l;
            split2(b.x, b.y, h, l);
            *(uint32_t*)&Bhi[lr * IPITCH + lc + v * 4]     = h;
            *(uint32_t*)&Blo[lr * IPITCH + lc + v * 4]     = l;
            split2(b.z, b.w, h, l);
            *(uint32_t*)&Bhi[lr * IPITCH + lc + v * 4 + 2] = h;
            *(uint32_t*)&Blo[lr * IPITCH + lc + v * 4 + 2] = l;
        }
        __syncthreads();

        #pragma unroll
        for (int kk = 0; kk < 2; kk++) {
            const int kb = kk * 16 + tg * 2;
            uint32_t ah[4][4], al[4][4];
            #pragma unroll
            for (int mi = 0; mi < 4; mi++) {
                int r0 = wm * 64 + mi * 16 + gq;
                ah[mi][0] = *(uint32_t*)&Ahi[r0 * IPITCH + kb];
                ah[mi][1] = *(uint32_t*)&Ahi[(r0 + 8) * IPITCH + kb];
                ah[mi][2] = *(uint32_t*)&Ahi[r0 * IPITCH + kb + 8];
                ah[mi][3] = *(uint32_t*)&Ahi[(r0 + 8) * IPITCH + kb + 8];
                al[mi][0] = *(uint32_t*)&Alo[r0 * IPITCH + kb];
                al[mi][1] = *(uint32_t*)&Alo[(r0 + 8) * IPITCH + kb];
                al[mi][2] = *(uint32_t*)&Alo[r0 * IPITCH + kb + 8];
                al[mi][3] = *(uint32_t*)&Alo[(r0 + 8) * IPITCH + kb + 8];
            }
            #pragma unroll
            for (int ni = 0; ni < 4; ni++) {
                int n0 = wn * 32 + ni * 8 + gq;
                uint32_t bh0 = *(uint32_t*)&Bhi[n0 * IPITCH + kb];
                uint32_t bh1 = *(uint32_t*)&Bhi[n0 * IPITCH + kb + 8];
                uint32_t bl0 = *(uint32_t*)&Blo[n0 * IPITCH + kb];
                uint32_t bl1 = *(uint32_t*)&Blo[n0 * IPITCH + kb + 8];
                #pragma unroll
                for (int mi = 0; mi < 4; mi++)
                    MMA(acc[mi][ni], ah[mi][0], ah[mi][1], ah[mi][2], ah[mi][3], bh0, bh1);
                #pragma unroll
                for (int mi = 0; mi < 4; mi++)
                    MMA(acc[mi][ni], ah[mi][0], ah[mi][1], ah[mi][2], ah[mi][3], bl0, bl1);
                #pragma unroll
                for (int mi = 0; mi < 4; mi++)
                    MMA(acc[mi][ni], al[mi][0], al[mi][1], al[mi][2], al[mi][3], bh0, bh1);
            }
        }
    }

    // epilogue: + bias, scatter time-major into g_xg
    #pragma unroll
    for (int mi = 0; mi < 4; mi++) {
        int row0 = bm * 128 + wm * 64 + mi * 16 + gq;
        int b0_ = row0 >> 9,       s0_ = row0 & 511;
        int b1_ = (row0 + 8) >> 9, s1_ = (row0 + 8) & 511;
        #pragma unroll
        for (int ni = 0; ni < 4; ni++) {
            int col = col0 + wn * 32 + ni * 8 + tg * 2;
            float2 bb = {bg[col], bg[col + 1]};
            *(float2*)&g_xg[g][s0_][b0_][col] = make_float2(acc[mi][ni][0] + bb.x, acc[mi][ni][1] + bb.y);
            *(float2*)&g_xg[g][s1_][b1_][col] = make_float2(acc[mi][ni][2] + bb.x, acc[mi][ni][3] + bb.y);
        }
    }
}

// ---------------------------------------------------------------------------
// K2: persistent HMMA scan. 96 CTAs x 256 thr.
// Per CTA: gate(3) x coltile(4: 256 U-cols) x ksplit(8: K=128).
// U slice -> SMEM bf16 hi/lo ONCE (resident all 512 steps). Per step:
// stage h (bf16 hi/lo, 32KB), warp-tiled HMMA (M=64 batch, N=32/warp, K=128),
// write partials, grid barrier, fused gate/state update, barrier.
// SMEM pitch 136 bf16 (68 words == 4 mod 32 -> conflict-free fragments).
// ---------------------------------------------------------------------------
#define SPITCH 136
#define OFF_U_HI 0
#define OFF_U_LO (OFF_U_HI + 256 * SPITCH * 2)   //  69632
#define OFF_H_HI (OFF_U_LO + 256 * SPITCH * 2)   // 139264
#define OFF_H_LO (OFF_H_HI + 64 * SPITCH * 2)    // 156672
#define SMEM_SCAN (OFF_H_LO + 64 * SPITCH * 2)   // 174080

__global__ __launch_bounds__(NTHR_SCAN) void k_scan(
    const float* __restrict__ Uf, const float* __restrict__ Uo, const float* __restrict__ Uc,
    float* __restrict__ out)
{
    extern __shared__ char smem[];
    uint16_t* Uh = (uint16_t*)(smem + OFF_U_HI);
    uint16_t* Ul = (uint16_t*)(smem + OFF_U_LO);
    uint16_t* Hh = (uint16_t*)(smem + OFF_H_HI);
    uint16_t* Hl = (uint16_t*)(smem + OFF_H_LO);

    const int cta  = blockIdx.x;          // 0..95
    const int gate = cta >> 5;            // 0..2
    const int ct   = (cta >> 3) & 3;      // coltile: 256 cols
    const int ks   = cta & 7;             // ksplit: 128 k
    const int kbeg = ks * KCHUNK;
    const int colbase = ct * 256;

    const float* Ug = (gate == 0) ? Uf : (gate == 1) ? Uo : Uc;

    const int tid  = threadIdx.x;
    const int wid  = tid >> 5;            // 0..7 -> n-split (32 cols each)
    const int lane = tid & 31;
    const int gq   = lane >> 2;
    const int tg   = lane & 3;
    const int gtid = cta * NTHR_SCAN + tid;

    // ---- convert this CTA's U slice to bf16 hi/lo in SMEM (once) ----
    #pragma unroll
    for (int i = 0; i < 32; i++) {
        int q = tid + i * NTHR_SCAN;      // 0..8191 float4 slots
        int row = q >> 5;                 // 0..255 (U output col)
        int k   = (q & 31) << 2;          // 0..124
        float4 u = *(const float4*)(Ug + (size_t)(colbase + row) * HH + kbeg + k);
        uint32_t h, l;
        split2(u.x, u.y, h, l);
        *(uint32_t*)&Uh[row * SPITCH + k]     = h;
        *(uint32_t*)&Ul[row * SPITCH + k]     = l;
        split2(u.z, u.w, h, l);
        *(uint32_t*)&Uh[row * SPITCH + k + 2] = h;
        *(uint32_t*)&Ul[row * SPITCH + k + 2] = l;
    }

    // ---- zero state (graph replays must not inherit) ----
    for (int i = gtid; i < BB * HH; i += SCAN_THREADS) {
        g_h[i] = 0.0f;
        g_c[i] = 0.0f;
        g_hb_hi[i] = __ushort_as_bfloat16(0);
        g_hb_lo[i] = __ushort_as_bfloat16(0);
    }
    grid_sync();

    for (int t = 0; t < SS; t++) {
        // ---- stage h tiles (64 x 128 bf16, hi+lo) into SMEM ----
        #pragma unroll
        for (int i = 0; i < 4; i++) {
            int q = tid + i * NTHR_SCAN;  // 0..1023 uint4 slots per term
            int row = q >> 4;             // 0..63 (batch)
            int pos = q & 15;             // 16B chunk
            const char* sh = (const char*)g_hb_hi + (size_t)row * 2048 + kbeg * 2 + pos * 16;
            const char* sl = (const char*)g_hb_lo + (size_t)row * 2048 + kbeg * 2 + pos * 16;
            *(uint4*)((char*)Hh + row * (SPITCH * 2) + pos * 16) = *(const uint4*)sh;
            *(uint4*)((char*)Hl + row * (SPITCH * 2) + pos * 16) = *(const uint4*)sl;
        }
        __syncthreads();

        // ---- HMMA: D[64 b][32 cols] per warp, K=128, 3-term split ----
        float acc[4][4][4] = {};
        #pragma unroll 2
        for (int kk = 0; kk < 8; kk++) {
            const int kb = kk * 16 + tg * 2;
            uint32_t ah[4][4], al[4][4];
            #pragma unroll
            for (int mi = 0; mi < 4; mi++) {
                int r0 = mi * 16 + gq;
                ah[mi][0] = *(uint32_t*)&Hh[r0 * SPITCH + kb];
                ah[mi][1] = *(uint32_t*)&Hh[(r0 + 8) * SPITCH + kb];
                ah[mi][2] = *(uint32_t*)&Hh[r0 * SPITCH + kb + 8];
                ah[mi][3] = *(uint32_t*)&Hh[(r0 + 8) * SPITCH + kb + 8];
                al[mi][0] = *(uint32_t*)&Hl[r0 * SPITCH + kb];
                al[mi][1] = *(uint32_t*)&Hl[(r0 + 8) * SPITCH + kb];
                al[mi][2] = *(uint32_t*)&Hl[r0 * SPITCH + kb + 8];
                al[mi][3] = *(uint32_t*)&Hl[(r0 + 8) * SPITCH + kb + 8];
            }
            #pragma unroll
            for (int ni = 0; ni < 4; ni++) {
                int n0 = wid * 32 + ni * 8 + gq;
                uint32_t bh0 = *(uint32_t*)&Uh[n0 * SPITCH + kb];
                uint32_t bh1 = *(uint32_t*)&Uh[n0 * SPITCH + kb + 8];
                uint32_t bl0 = *(uint32_t*)&Ul[n0 * SPITCH + kb];
                uint32_t bl1 = *(uint32_t*)&Ul[n0 * SPITCH + kb + 8];
                #pragma unroll
                for (int mi = 0; mi < 4; mi++)
                    MMA(acc[mi][ni], ah[mi][0], ah[mi][1], ah[mi][2], ah[mi][3], bh0, bh1);
                #pragma unroll
                for (int mi = 0; mi < 4; mi++)
                    MMA(acc[mi][ni], ah[mi][0], ah[mi][1], ah[mi][2], ah[mi][3], bl0, bl1);
                #pragma unroll
                for (int mi = 0; mi < 4; mi++)
                    MMA(acc[mi][ni], al[mi][0], al[mi][1], al[mi][2], al[mi][3], bh0, bh1);
            }
        }

        // ---- write partials D[b][col] ----
        #pragma unroll
        for (int mi = 0; mi < 4; mi++) {
            int b0_ = mi * 16 + gq;
            #pragma unroll
            for (int ni = 0; ni < 4; ni++) {
                int col = colbase + wid * 32 + ni * 8 + tg * 2;
                *(float2*)&g_part[ks][gate][b0_][col]     = make_float2(acc[mi][ni][0], acc[mi][ni][1]);
                *(float2*)&g_part[ks][gate][b0_ + 8][col] = make_float2(acc[mi][ni][2], acc[mi][ni][3]);
            }
        }
        grid_sync();

        // ---- phase B: reduce partials, gates, state update ----
        for (int idx = gtid; idx < BB * HH; idx += SCAN_THREADS) {
            int b_  = idx >> 10;
            int col = idx & 1023;
            float pf = g_xg[0][t][b_][col];
            float po = g_xg[1][t][b_][col];
            float pc = g_xg[2][t][b_][col];
            #pragma unroll
            for (int k = 0; k < KSPLIT; k++) {
                pf += g_part[k][0][b_][col];
                po += g_part[k][1][b_][col];
                pc += g_part[k][2][b_][col];
            }
            float f = 1.0f / (1.0f + __expf(-pf));
            float o = 1.0f / (1.0f + __expf(-po));
            float c = f * g_c[idx] + tanhf(pc);
            float h = o * c;
            g_c[idx] = c;
            g_h[idx] = h;
            __nv_bfloat16 hh = __float2bfloat16_rn(h);
            g_hb_hi[idx] = hh;
            g_hb_lo[idx] = __float2bfloat16_rn(h - __bfloat162float(hh));
            out[((size_t)b_ * SS + t) * HH + col] = h;
        }
        grid_sync();
    }

    // ---- tail: (output[B,S,H], h[1,B,H], c[1,B,H]) ----
    for (int i = gtid; i < BB * HH; i += SCAN_THREADS) {
        out[(size_t)BB * SS * HH + i]           = g_h[i];
        out[(size_t)BB * SS * HH + BB * HH + i] = g_c[i];
    }
}

extern "C" void kernel_launch(void* const* d_in, const int* in_sizes, int n_in,
                              void* d_out, int out_size) {
    const float* X  = (const float*)d_in[0];
    const float* Wf = (const float*)d_in[1];
    const float* Uf = (const float*)d_in[2];
    const float* bf = (const float*)d_in[3];
    // d_in[4..6] = W_i/U_i/b_i: gate i is computed-but-unused in the reference.
    const float* Wo = (const float*)d_in[7];
    const float* Uo = (const float*)d_in[8];
    const float* bo = (const float*)d_in[9];
    const float* Wc = (const float*)d_in[10];
    const float* Uc = (const float*)d_in[11];
    const float* bc = (const float*)d_in[12];
    float* out = (float*)d_out;

    cudaFuncSetAttribute(k_scan, cudaFuncAttributeMaxDynamicSharedMemorySize, SMEM_SCAN);

    k_ingemm<<<dim3(256, 24), 256>>>(X, Wf, Wo, Wc, bf, bo, bc);
    k_scan<<<NCTA_SCAN, NTHR_SCAN, SMEM_SCAN>>>(Uf, Uo, Uc, out);
}

// round 5
// speedup vs baseline: 2.6818x; 1.0916x over previous
#include <cuda_runtime.h>
#include <cuda_bf16.h>
#include <math.h>
#include <stdint.h>

#define BB 64
#define SS 512
#define II 1024
#define HH 1024

#define KSPLIT 4                 // scan K-splits (chunk = 256)
#define KCHUNK 256
#define NCTA_SCAN 96             // 3 gates x 8 coltiles(128) x 4 ksplits
#define NTHR_SCAN 256
#define SCAN_THREADS (NCTA_SCAN * NTHR_SCAN)

// ---------------------------------------------------------------------------
// Device globals (no allocation allowed anywhere)
// ---------------------------------------------------------------------------
__device__ float g_xg[3][SS][BB][HH];           // input-side pre-activations
__device__ float g_c[BB * HH];
__device__ float g_part[KSPLIT][3][BB][HH];     // recurrent GEMM partials
__device__ __nv_bfloat16 g_hb_hi[BB * HH];      // h split into bf16 hi/lo
__device__ __nv_bfloat16 g_hb_lo[BB * HH];
__device__ __nv_bfloat16 g_xb_hi[BB * SS * II]; // X pre-split to bf16 hi/lo
__device__ __nv_bfloat16 g_xb_lo[BB * SS * II];
__device__ __nv_bfloat16 g_wb_hi[3][HH * II];   // W_f/o/c pre-split
__device__ __nv_bfloat16 g_wb_lo[3][HH * II];

// grid barrier state: 8 arrival buckets (12 CTAs each) + release generation
__device__ unsigned g_cnt[8];
__device__ unsigned g_gen;

__device__ __forceinline__ void grid_sync(unsigned gen) {
    __threadfence();
    __syncthreads();
    if (blockIdx.x == 0) {
        if (threadIdx.x == 0) atomicAdd(&g_cnt[0], 1u);
        if (threadIdx.x < 8) {
            while (*(volatile unsigned*)&g_cnt[threadIdx.x] < 12u * gen) { }
        }
        __syncthreads();
        if (threadIdx.x == 0) atomicExch(&g_gen, gen);
    } else {
        if (threadIdx.x == 0) {
            atomicAdd(&g_cnt[blockIdx.x & 7], 1u);
            while (*(volatile unsigned*)&g_gen < gen) { }
        }
        __syncthreads();
    }
    __threadfence();
}

__global__ void k_reset() {
    if (threadIdx.x < 8) g_cnt[threadIdx.x] = 0;
    if (threadIdx.x == 0) g_gen = 0;
}

// ---------------------------------------------------------------------------
// HMMA helper + bf16 hi/lo split
// ---------------------------------------------------------------------------
#define MMA(d, a0, a1, a2, a3, b0, b1)                                        \
    asm volatile("mma.sync.aligned.m16n8k16.row.col.f32.bf16.bf16.f32 "       \
        "{%0,%1,%2,%3}, {%4,%5,%6,%7}, {%8,%9}, {%0,%1,%2,%3};"               \
        : "+f"((d)[0]), "+f"((d)[1]), "+f"((d)[2]), "+f"((d)[3])              \
        : "r"(a0), "r"(a1), "r"(a2), "r"(a3), "r"(b0), "r"(b1))

__device__ __forceinline__ void split2(float x0, float x1, uint32_t& hi, uint32_t& lo) {
    __nv_bfloat16 h0 = __float2bfloat16_rn(x0);
    __nv_bfloat16 h1 = __float2bfloat16_rn(x1);
    __nv_bfloat16 l0 = __float2bfloat16_rn(x0 - __bfloat162float(h0));
    __nv_bfloat16 l1 = __float2bfloat16_rn(x1 - __bfloat162float(h1));
    hi = ((uint32_t)__bfloat16_as_ushort(h1) << 16) | (uint32_t)__bfloat16_as_ushort(h0);
    lo = ((uint32_t)__bfloat16_as_ushort(l1) << 16) | (uint32_t)__bfloat16_as_ushort(l0);
}

__device__ __forceinline__ float fast_sigmoid(float x) {
    return __fdividef(1.0f, 1.0f + __expf(-x));
}
__device__ __forceinline__ float fast_tanh(float x) {
    float ax = fabsf(x);
    float e  = __expf(ax + ax);
    float r  = 1.0f - __fdividef(2.0f, e + 1.0f);
    return copysignf(r, x);
}

// ---------------------------------------------------------------------------
// K0: convert fp32 -> bf16 hi/lo once. which: 0 = X, 1..3 = W_{f,o,c}
// ---------------------------------------------------------------------------
__global__ __launch_bounds__(256) void k_conv(const float* __restrict__ src,
                                              int which, int n4) {
    __nv_bfloat16* dhi = (which == 0) ? g_xb_hi : g_wb_hi[which - 1];
    __nv_bfloat16* dlo = (which == 0) ? g_xb_lo : g_wb_lo[which - 1];
    int stride = gridDim.x * 256;
    for (int q = blockIdx.x * 256 + threadIdx.x; q < n4; q += stride) {
        float4 v = ((const float4*)src)[q];
        uint32_t h0, l0, h1, l1;
        split2(v.x, v.y, h0, l0);
        split2(v.z, v.w, h1, l1);
        ((uint2*)dhi)[q] = make_uint2(h0, h1);
        ((uint2*)dlo)[q] = make_uint2(l0, l1);
    }
}

// ---------------------------------------------------------------------------
// K1: input-side GEMM via HMMA bf16 3-term split (pre-converted operands).
// M = 32768, N = 3x1024, K = 1024. CTA 128x128, k-step 32, 8 warps (2m x 4n).
// ---------------------------------------------------------------------------
#define IPITCH 40
__global__ __launch_bounds__(256, 2) void k_ingemm(
    const float* __restrict__ bf, const float* __restrict__ bo, const float* __restrict__ bc)
{
    __shared__ __align__(16) uint16_t Ahi[128 * IPITCH], Alo[128 * IPITCH];
    __shared__ __align__(16) uint16_t Bhi[128 * IPITCH], Blo[128 * IPITCH];

    const int bm = blockIdx.x;            // 0..255
    const int bn = blockIdx.y;            // 0..23
    const int g  = bn >> 3;
    const int col0 = (bn & 7) << 7;

    const float* bg = (g == 0) ? bf : (g == 1) ? bo : bc;

    const int tid  = threadIdx.x;
    const int wid  = tid >> 5;
    const int lane = tid & 31;
    const int gq   = lane >> 2;
    const int tg   = lane & 3;
    const int wm   = wid >> 2;
    const int wn   = wid & 3;

    const int lr = tid >> 1;              // loader row 0..127
    const int lq = tid & 1;

    const __nv_bfloat16* Aph = g_xb_hi + (size_t)(bm * 128 + lr) * II;
    const __nv_bfloat16* Apl = g_xb_lo + (size_t)(bm * 128 + lr) * II;
    const __nv_bfloat16* Bph = g_wb_hi[g] + (size_t)(col0 + lr) * II;
    const __nv_bfloat16* Bpl = g_wb_lo[g] + (size_t)(col0 + lr) * II;

    float acc[4][4][4] = {};

    for (int k0 = 0; k0 < II; k0 += 32) {
        __syncthreads();
        #pragma unroll
        for (int j = 0; j < 2; j++) {
            const int kb = lq * 16 + j * 8;
            *(uint4*)&Ahi[lr * IPITCH + kb] = *(const uint4*)(Aph + k0 + kb);
            *(uint4*)&Alo[lr * IPITCH + kb] = *(const uint4*)(Apl + k0 + kb);
            *(uint4*)&Bhi[lr * IPITCH + kb] = *(const uint4*)(Bph + k0 + kb);
            *(uint4*)&Blo[lr * IPITCH + kb] = *(const uint4*)(Bpl + k0 + kb);
        }
        __syncthreads();

        #pragma unroll
        for (int kk = 0; kk < 2; kk++) {
            const int kb = kk * 16 + tg * 2;
            uint32_t ah[4][4], al[4][4];
            #pragma unroll
            for (int mi = 0; mi < 4; mi++) {
                int r0 = wm * 64 + mi * 16 + gq;
                ah[mi][0] = *(uint32_t*)&Ahi[r0 * IPITCH + kb];
                ah[mi][1] = *(uint32_t*)&Ahi[(r0 + 8) * IPITCH + kb];
                ah[mi][2] = *(uint32_t*)&Ahi[r0 * IPITCH + kb + 8];
                ah[mi][3] = *(uint32_t*)&Ahi[(r0 + 8) * IPITCH + kb + 8];
                al[mi][0] = *(uint32_t*)&Alo[r0 * IPITCH + kb];
                al[mi][1] = *(uint32_t*)&Alo[(r0 + 8) * IPITCH + kb];
                al[mi][2] = *(uint32_t*)&Alo[r0 * IPITCH + kb + 8];
                al[mi][3] = *(uint32_t*)&Alo[(r0 + 8) * IPITCH + kb + 8];
            }
            #pragma unroll
            for (int ni = 0; ni < 4; ni++) {
                int n0 = wn * 32 + ni * 8 + gq;
                uint32_t bh0 = *(uint32_t*)&Bhi[n0 * IPITCH + kb];
                uint32_t bh1 = *(uint32_t*)&Bhi[n0 * IPITCH + kb + 8];
                uint32_t bl0 = *(uint32_t*)&Blo[n0 * IPITCH + kb];
                uint32_t bl1 = *(uint32_t*)&Blo[n0 * IPITCH + kb + 8];
                #pragma unroll
                for (int mi = 0; mi < 4; mi++)
                    MMA(acc[mi][ni], ah[mi][0], ah[mi][1], ah[mi][2], ah[mi][3], bh0, bh1);
                #pragma unroll
                for (int mi = 0; mi < 4; mi++)
                    MMA(acc[mi][ni], ah[mi][0], ah[mi][1], ah[mi][2], ah[mi][3], bl0, bl1);
                #pragma unroll
                for (int mi = 0; mi < 4; mi++)
                    MMA(acc[mi][ni], al[mi][0], al[mi][1], al[mi][2], al[mi][3], bh0, bh1);
            }
        }
    }

    #pragma unroll
    for (int mi = 0; mi < 4; mi++) {
        int row0 = bm * 128 + wm * 64 + mi * 16 + gq;
        int b0_ = row0 >> 9,       s0_ = row0 & 511;
        int b1_ = (row0 + 8) >> 9, s1_ = (row0 + 8) & 511;
        #pragma unroll
        for (int ni = 0; ni < 4; ni++) {
            int col = col0 + wn * 32 + ni * 8 + tg * 2;
            float2 bb = {bg[col], bg[col + 1]};
            *(float2*)&g_xg[g][s0_][b0_][col] = make_float2(acc[mi][ni][0] + bb.x, acc[mi][ni][1] + bb.y);
            *(float2*)&g_xg[g][s1_][b1_][col] = make_float2(acc[mi][ni][2] + bb.x, acc[mi][ni][3] + bb.y);
        }
    }
}

// ---------------------------------------------------------------------------
// K2: persistent HMMA scan. 96 CTAs x 256 thr.
// Per CTA: gate(3) x coltile(8: 128 cols) x ksplit(4: K=256).
// SPITCH 264 elems (132 words == 4 mod 32 -> conflict-free fragments).
// ---------------------------------------------------------------------------
#define SPITCH 264
#define OFF_U_HI 0
#define OFF_U_LO (OFF_U_HI + 128 * SPITCH * 2)   //  67584
#define OFF_H_HI (OFF_U_LO + 128 * SPITCH * 2)   // 135168
#define OFF_H_LO (OFF_H_HI + 64 * SPITCH * 2)    // 168960
#define SMEM_SCAN (OFF_H_LO + 64 * SPITCH * 2)   // 202752

__global__ __launch_bounds__(NTHR_SCAN) void k_scan(
    const float* __restrict__ Uf, const float* __restrict__ Uo, const float* __restrict__ Uc,
    float* __restrict__ out)
{
    extern __shared__ char smem[];
    uint16_t* Uh = (uint16_t*)(smem + OFF_U_HI);
    uint16_t* Ul = (uint16_t*)(smem + OFF_U_LO);
    uint16_t* Hh = (uint16_t*)(smem + OFF_H_HI);
    uint16_t* Hl = (uint16_t*)(smem + OFF_H_LO);

    const int cta  = blockIdx.x;          // 0..95
    const int gate = cta >> 5;            // 0..2
    const int ct   = (cta >> 2) & 7;      // coltile: 128 cols
    const int ks   = cta & 3;             // ksplit: 256 k
    const int kbeg = ks * KCHUNK;
    const int colbase = ct * 128;

    const float* Ug = (gate == 0) ? Uf : (gate == 1) ? Uo : Uc;

    const int tid  = threadIdx.x;
    const int wid  = tid >> 5;            // 0..7 -> 16 cols each
    const int lane = tid & 31;
    const int gq   = lane >> 2;
    const int tg   = lane & 3;
    const int gtid = cta * NTHR_SCAN + tid;

    // ---- convert this CTA's U slice (128 x 256) to bf16 hi/lo in SMEM ----
    #pragma unroll
    for (int i = 0; i < 32; i++) {
        int q = tid + i * NTHR_SCAN;      // 0..8191 float4 slots
        int row = q >> 6;                 // 0..127 (output col)
        int k   = (q & 63) << 2;          // 0..252
        float4 u = *(const float4*)(Ug + (size_t)(colbase + row) * HH + kbeg + k);
        uint32_t h, l;
        split2(u.x, u.y, h, l);
        *(uint32_t*)&Uh[row * SPITCH + k]     = h;
        *(uint32_t*)&Ul[row * SPITCH + k]     = l;
        split2(u.z, u.w, h, l);
        *(uint32_t*)&Uh[row * SPITCH + k + 2] = h;
        *(uint32_t*)&Ul[row * SPITCH + k + 2] = l;
    }

    // ---- zero state (graph replays must not inherit) ----
    for (int i = gtid; i < BB * HH; i += SCAN_THREADS) {
        g_c[i] = 0.0f;
        g_hb_hi[i] = __ushort_as_bfloat16(0);
        g_hb_lo[i] = __ushort_as_bfloat16(0);
    }
    unsigned gen = 1;
    grid_sync(gen++);

    for (int t = 0; t < SS; t++) {
        // ---- stage h tiles (64 x 256 bf16, hi+lo) into SMEM ----
        #pragma unroll
        for (int i = 0; i < 8; i++) {
            int q = tid + i * NTHR_SCAN;  // 0..2047 uint4 slots per term
            int row = q >> 5;             // 0..63 (batch)
            int pos = q & 31;             // 16B chunk within 512B row
            const char* sh = (const char*)g_hb_hi + (size_t)row * 2048 + kbeg * 2 + pos * 16;
            const char* sl = (const char*)g_hb_lo + (size_t)row * 2048 + kbeg * 2 + pos * 16;
            *(uint4*)((char*)Hh + row * (SPITCH * 2) + pos * 16) = *(const uint4*)sh;
            *(uint4*)((char*)Hl + row * (SPITCH * 2) + pos * 16) = *(const uint4*)sl;
        }
        __syncthreads();

        // ---- HMMA: D[64 b][16 cols] per warp, K=256, 3-term split ----
        float acc[4][2][4] = {};
        #pragma unroll 2
        for (int kk = 0; kk < 16; kk++) {
            const int kb = kk * 16 + tg * 2;
            uint32_t ah[4][4], al[4][4];
            #pragma unroll
            for (int mi = 0; mi < 4; mi++) {
                int r0 = mi * 16 + gq;
                ah[mi][0] = *(uint32_t*)&Hh[r0 * SPITCH + kb];
                ah[mi][1] = *(uint32_t*)&Hh[(r0 + 8) * SPITCH + kb];
                ah[mi][2] = *(uint32_t*)&Hh[r0 * SPITCH + kb + 8];
                ah[mi][3] = *(uint32_t*)&Hh[(r0 + 8) * SPITCH + kb + 8];
                al[mi][0] = *(uint32_t*)&Hl[r0 * SPITCH + kb];
                al[mi][1] = *(uint32_t*)&Hl[(r0 + 8) * SPITCH + kb];
                al[mi][2] = *(uint32_t*)&Hl[r0 * SPITCH + kb + 8];
                al[mi][3] = *(uint32_t*)&Hl[(r0 + 8) * SPITCH + kb + 8];
            }
            #pragma unroll
            for (int ni = 0; ni < 2; ni++) {
                int n0 = wid * 16 + ni * 8 + gq;
                uint32_t bh0 = *(uint32_t*)&Uh[n0 * SPITCH + kb];
                uint32_t bh1 = *(uint32_t*)&Uh[n0 * SPITCH + kb + 8];
                uint32_t bl0 = *(uint32_t*)&Ul[n0 * SPITCH + kb];
                uint32_t bl1 = *(uint32_t*)&Ul[n0 * SPITCH + kb + 8];
                #pragma unroll
                for (int mi = 0; mi < 4; mi++)
                    MMA(acc[mi][ni], ah[mi][0], ah[mi][1], ah[mi][2], ah[mi][3], bh0, bh1);
                #pragma unroll
                for (int mi = 0; mi < 4; mi++)
                    MMA(acc[mi][ni], ah[mi][0], ah[mi][1], ah[mi][2], ah[mi][3], bl0, bl1);
                #pragma unroll
                for (int mi = 0; mi < 4; mi++)
                    MMA(acc[mi][ni], al[mi][0], al[mi][1], al[mi][2], al[mi][3], bh0, bh1);
            }
        }

        // ---- write partials ----
        #pragma unroll
        for (int mi = 0; mi < 4; mi++) {
            int b0_ = mi * 16 + gq;
            #pragma unroll
            for (int ni = 0; ni < 2; ni++) {
                int col = colbase + wid * 16 + ni * 8 + tg * 2;
                *(float2*)&g_part[ks][gate][b0_][col]     = make_float2(acc[mi][ni][0], acc[mi][ni][1]);
                *(float2*)&g_part[ks][gate][b0_ + 8][col] = make_float2(acc[mi][ni][2], acc[mi][ni][3]);
            }
        }
        grid_sync(gen++);

        // ---- phase B: float4 per thread; 16384 threads active ----
        if (gtid < 16384) {
            int b_  = gtid >> 8;
            int col = (gtid & 255) << 2;
            float4 pf = *(const float4*)&g_xg[0][t][b_][col];
            float4 po = *(const float4*)&g_xg[1][t][b_][col];
            float4 pc = *(const float4*)&g_xg[2][t][b_][col];
            #pragma unroll
            for (int k = 0; k < KSPLIT; k++) {
                float4 v;
                v = *(const float4*)&g_part[k][0][b_][col];
                pf.x += v.x; pf.y += v.y; pf.z += v.z; pf.w += v.w;
                v = *(const float4*)&g_part[k][1][b_][col];
                po.x += v.x; po.y += v.y; po.z += v.z; po.w += v.w;
                v = *(const float4*)&g_part[k][2][b_][col];
                pc.x += v.x; pc.y += v.y; pc.z += v.z; pc.w += v.w;
            }
            float4 cold = *(const float4*)&g_c[gtid << 2];
            float4 cn, hn;
            cn.x = fast_sigmoid(pf.x) * cold.x + fast_tanh(pc.x);
            cn.y = fast_sigmoid(pf.y) * cold.y + fast_tanh(pc.y);
            cn.z = fast_sigmoid(pf.z) * cold.z + fast_tanh(pc.z);
            cn.w = fast_sigmoid(pf.w) * cold.w + fast_tanh(pc.w);
            hn.x = fast_sigmoid(po.x) * cn.x;
            hn.y = fast_sigmoid(po.y) * cn.y;
            hn.z = fast_sigmoid(po.z) * cn.z;
            hn.w = fast_sigmoid(po.w) * cn.w;
            *(float4*)&g_c[gtid << 2] = cn;

            uint32_t h01, l01, h23, l23;
            split2(hn.x, hn.y, h01, l01);
            split2(hn.z, hn.w, h23, l23);
            *(uint2*)&g_hb_hi[gtid << 2] = make_uint2(h01, h23);
            *(uint2*)&g_hb_lo[gtid << 2] = make_uint2(l01, l23);

            *(float4*)&out[((size_t)b_ * SS + t) * HH + col] = hn;
            if (t == SS - 1) {
                *(float4*)&out[(size_t)BB * SS * HH + (gtid << 2)] = hn;
                *(float4*)&out[(size_t)BB * SS * HH + BB * HH + (gtid << 2)] = cn;
            }
        }
        grid_sync(gen++);
    }
}

extern "C" void kernel_launch(void* const* d_in, const int* in_sizes, int n_in,
                              void* d_out, int out_size) {
    const float* X  = (const float*)d_in[0];
    const float* Wf = (const float*)d_in[1];
    const float* Uf = (const float*)d_in[2];
    const float* bf = (const float*)d_in[3];
    // d_in[4..6] = W_i/U_i/b_i: gate i is computed-but-unused in the reference.
    const float* Wo = (const float*)d_in[7];
    const float* Uo = (const float*)d_in[8];
    const float* bo = (const float*)d_in[9];
    const float* Wc = (const float*)d_in[10];
    const float* Uc = (const float*)d_in[11];
    const float* bc = (const float*)d_in[12];
    float* out = (float*)d_out;

    cudaFuncSetAttribute(k_scan, cudaFuncAttributeMaxDynamicSharedMemorySize, SMEM_SCAN);

    k_reset<<<1, 32>>>();
    k_conv<<<4096, 256>>>(X,  0, (BB * SS * II) / 4);
    k_conv<<<1024, 256>>>(Wf, 1, (HH * II) / 4);
    k_conv<<<1024, 256>>>(Wo, 2, (HH * II) / 4);
    k_conv<<<1024, 256>>>(Wc, 3, (HH * II) / 4);
    k_ingemm<<<dim3(256, 24), 256>>>(bf, bo, bc);
    k_scan<<<NCTA_SCAN, NTHR_SCAN, SMEM_SCAN>>>(Uf, Uo, Uc, out);
}